// round 14
// baseline (speedup 1.0000x reference)
#include <cuda_runtime.h>
#include <cuda_fp16.h>
#include <math_constants.h>

// Problem-shape constants (fixed by setup_inputs)
#define NN   50000
#define EN   400000
#define EEN  800000
#define CN   800000

#define FULLMASK 0xffffffffu

// ---------------- static scratch (no allocation allowed) ----------------
__device__ __half  g_zh[(size_t)EN * 32];     // [E,32] z (fp16, 64 B rows)
__device__ float4 g_va[(size_t)EN * 2];       // [E]: {vsum float4, ak float4}
__device__ float2 g_sn[(size_t)EN * 4];       // [E,4] interleaved (exp-sum, exp*vsum)
__device__ float4 g_S3[NN];                   // stage3 per-head exp-sum
__device__ float  g_whk[4];
__device__ float  g_wv[4];
// fp16 M-table B-fragments, lane-exact m16n8k16 layout:
// idx = ((((h*2+side)*4+nt)*2+ks)*2+reg)*32 + lane   (side 0=q [pre-scaled], 1=k)
__device__ unsigned int g_mfrag[4096];
__device__ float  g_ck[32 * 4];               // ak weights: 0.177 * W2k_fold . bq_fold
__device__ float4 g_W2v[32];                  // W2 @ wvh  [32,4]
__device__ float4 g_bv;                       // b2 @ wvh

__device__ __forceinline__ unsigned long long pk2(float a, float b) {
    unsigned long long r;
    asm("mov.b64 %0, {%1, %2};" : "=l"(r) : "f"(a), "f"(b));
    return r;
}
__device__ __forceinline__ void ffma2(unsigned long long& d,
                                      unsigned long long a,
                                      unsigned long long b) {
    asm("fma.rn.f32x2 %0, %1, %2, %0;" : "+l"(d) : "l"(a), "l"(b));
}
__device__ __forceinline__ float2 unpk(unsigned long long v) {
    float2 r;
    asm("mov.b64 {%0, %1}, %2;" : "=f"(r.x), "=f"(r.y) : "l"(v));
    return r;
}
__device__ __forceinline__ unsigned smem_u32(const void* p) {
    return (unsigned)__cvta_generic_to_shared(p);
}

// ---------------- K_prep_all: M fragment table + aux weights + S3 zero ----------------
__global__ void k_prep_all(const float* __restrict__ W2, const float* __restrict__ b2,
                           const float* __restrict__ Wq, const float* __restrict__ Wk,
                           const float* __restrict__ Wv,
                           const float* __restrict__ Wq2,
                           const float* __restrict__ Wk2,
                           const float* __restrict__ Wv2, int N) {
    const float SC = 0.17677669529663687f;    // 1/sqrt(32)
    int idx = blockIdx.x * 256 + threadIdx.x;
    if (idx < 4096) {                         // M-table B-fragments
        int lane = idx & 31;
        int reg  = (idx >> 5) & 1;
        int ks   = (idx >> 6) & 1;
        int nt   = (idx >> 7) & 3;
        int side = (idx >> 9) & 1;
        int h    = (idx >> 10) & 3;
        int col = h * 32 + nt * 8 + (lane >> 2);
        int k0  = ks * 16 + (lane & 3) * 2 + reg * 8;
        const float* Wx = side ? Wk : Wq;
        float v0 = 0.f, v1 = 0.f;
        for (int m = 0; m < 128; m++) {
            float wcol = Wx[m * 128 + col];
            v0 += W2[k0 * 128 + m] * wcol;
            v1 += W2[(k0 + 1) * 128 + m] * wcol;
        }
        if (side == 0) { v0 *= SC; v1 *= SC; }
        __half2 p = __floats2half2_rn(v0, v1);
        g_mfrag[idx] = *(unsigned int*)&p;
    } else if (idx < 4224) {                  // ck[32][4]: ak weights
        int i = idx - 4096;
        int m = i >> 2, h = i & 3;
        float s = 0.f;
        for (int j = 0; j < 32; j++) {
            int col = h * 32 + j;
            float w2kf = 0.f, bqf = 0.f;
            for (int mm = 0; mm < 128; mm++) {
                w2kf += W2[m * 128 + mm] * Wk[mm * 128 + col];
                bqf  += b2[mm] * Wq[mm * 128 + col];
            }
            s += w2kf * bqf;
        }
        g_ck[i] = s * SC;
    } else if (idx < 4352) {                  // W2v [32][4]
        int i = idx - 4224;
        int r = i >> 2, hh = i & 3;
        float s = 0.f;
        for (int m = 0; m < 128; m++) {
            float w = 0.f;
            for (int d = 0; d < 32; d++) w += Wv[m * 128 + hh * 32 + d];
            s += W2[r * 128 + m] * w;
        }
        ((float*)&g_W2v[r])[hh] = s;
    } else if (idx < 4356) {                  // bv
        int hh = idx - 4352;
        float s = 0.f;
        for (int m = 0; m < 128; m++) {
            float w = 0.f;
            for (int d = 0; d < 32; d++) w += Wv[m * 128 + hh * 32 + d];
            s += b2[m] * w;
        }
        ((float*)&g_bv)[hh] = s;
    } else if (idx < 4360) {                  // whk
        int h = idx - 4356;
        float qk = 0.f;
        for (int d = 0; d < 32; d++) qk += Wq2[h * 32 + d] * Wk2[h * 32 + d];
        g_whk[h] = qk * SC;
    } else if (idx < 4364) {                  // wv
        int h = idx - 4360;
        float vv = 0.f;
        for (int d = 0; d < 32; d++) vv += Wv2[h * 32 + d];
        g_wv[h] = vv;
    } else {                                  // zero g_S3
        int j = idx - 4480;
        if (j >= 0 && j < N)
            g_S3[j] = make_float4(0.f, 0.f, 0.f, 0.f);
    }
}

// ---------------- K1: edge MLP -> z (fp16) + vsum/ak ----------------
// Block = 256 threads = 8 warps, 64 edges. Layer-1 exact fp32 via
// transposed-ea SMEM + packed FFMA2; vsum & ak via per-lane SMEM dots.
// Prologue: zero g_sn/out + stage-3 S3 accumulation.
#define EASTR 10
#define ZSSTR 36
__global__ void __launch_bounds__(256) k_edge(
    const float* __restrict__ x, const int* __restrict__ ei,
    const float* __restrict__ ea,
    const float* __restrict__ W1, const float* __restrict__ b1,
    const int* __restrict__ nni,
    float* __restrict__ out, int N, int E, int C)
{
    __shared__ float  W1s[34 * 32];            // 4352 B
    __shared__ float  b1s[32];                 //  128 B
    __shared__ float  zs[8 * 8 * ZSSTR];       // 9216 B  fp32 z
    __shared__ float  eat[8 * 32 * EASTR];     // 10240 B transposed ea per warp
    __shared__ float4 W2vs[32];                //  512 B
    __shared__ float  cks[32 * 4];             //  512 B
    __shared__ float4 bvs;                     //   16 B

    int tid = threadIdx.x;

    // ---- folded zero-init + stage-3 S3 accumulation ----
    {
        int g = blockIdx.x * 256 + tid;
        const float4 z4 = make_float4(0.f, 0.f, 0.f, 0.f);
        if (g < E) {
            ((float4*)g_sn)[2 * g + 0] = z4;
            ((float4*)g_sn)[2 * g + 1] = z4;
        }
        if (g < N) out[g] = 0.f;
        if (g < C) {
            int ns = nni[g], nd = nni[C + g];
            float s = __ldg(x + ns) * __ldg(x + nd);
            float4 ev;
            ev.x = __expf(s * g_whk[0]);
            ev.y = __expf(s * g_whk[1]);
            ev.z = __expf(s * g_whk[2]);
            ev.w = __expf(s * g_whk[3]);
            atomicAdd(&g_S3[nd], ev);
        }
    }

    // ---- SMEM fills (small) ----
    for (int i = tid; i < 34 * 32; i += 256) W1s[i] = W1[i];
    if (tid < 32) b1s[tid] = b1[tid];
    if (tid < 32) W2vs[tid] = g_W2v[tid];
    if (tid < 128) cks[tid] = g_ck[tid];
    if (tid == 0) bvs = g_bv;

    int lane = tid & 31;
    int warp = tid >> 5;
    int e0w = blockIdx.x * 64 + warp * 8;   // this warp's 8 edges

    // ---- gather endpoint x values: lanes 0-7 -> xs, lanes 8-15 -> xd ----
    float xv = 0.f;
    if (lane < 16) {
        int e = e0w + (lane & 7);
        int idx = (lane < 8) ? ei[e] : ei[E + e];
        xv = __ldg(x + idx);
    }

    // ---- stage ea transposed: eat[m][edge] (per-warp tile) ----
    {
        float* eatw = eat + warp * 32 * EASTR;
        const float4* ea4 = (const float4*)(ea + (size_t)e0w * 32);
        #pragma unroll
        for (int r = 0; r < 2; r++) {
            float4 v = __ldg(ea4 + r * 32 + lane);
            int j  = r * 4 + (lane >> 3);
            int m0 = (lane & 7) * 4;
            eatw[(m0 + 0) * EASTR + j] = v.x;
            eatw[(m0 + 1) * EASTR + j] = v.y;
            eatw[(m0 + 2) * EASTR + j] = v.z;
            eatw[(m0 + 3) * EASTR + j] = v.w;
        }
    }
    __syncthreads();

    // ---- layer 1, packed over edge pairs (exact fp32 per lane) ----
    {
        float bb = b1s[lane];
        unsigned long long wr0 = pk2(W1s[lane], W1s[lane]);
        unsigned long long wr1 = pk2(W1s[32 + lane], W1s[32 + lane]);
        unsigned long long acc2[4];
        #pragma unroll
        for (int p = 0; p < 4; p++) {
            float xs0 = __shfl_sync(FULLMASK, xv, 2 * p);
            float xs1 = __shfl_sync(FULLMASK, xv, 2 * p + 1);
            float xd0 = __shfl_sync(FULLMASK, xv, 8 + 2 * p);
            float xd1 = __shfl_sync(FULLMASK, xv, 9 + 2 * p);
            acc2[p] = pk2(bb, bb);
            ffma2(acc2[p], wr0, pk2(xs0, xs1));
            ffma2(acc2[p], wr1, pk2(xd0, xd1));
        }
        const float* eatw = eat + warp * 32 * EASTR;
        #pragma unroll 8
        for (int m = 0; m < 32; m++) {
            float w = W1s[(2 + m) * 32 + lane];
            unsigned long long wp = pk2(w, w);
            const float* row = eatw + m * EASTR;
            #pragma unroll
            for (int p = 0; p < 4; p++) {
                float2 ep = *(const float2*)(row + 2 * p);
                ffma2(acc2[p], wp, pk2(ep.x, ep.y));
            }
        }
        float* zsw = zs + warp * 8 * ZSSTR;
        #pragma unroll
        for (int p = 0; p < 4; p++) {
            float2 zz = unpk(acc2[p]);
            zsw[(2 * p) * ZSSTR + lane] = fmaxf(zz.x, 0.f);
            zsw[(2 * p + 1) * ZSSTR + lane] = fmaxf(zz.y, 0.f);
        }
    }
    __syncwarp();

    // ---- vsum & ak: lane = (edge e = lane>>2, head h = lane&3), fp32 dots ----
    {
        int e = lane >> 2, h = lane & 3;
        const float* zsw = zs + warp * 8 * ZSSTR + e * ZSSTR;
        const float* wv = (const float*)W2vs;
        float av = ((const float*)&bvs)[h];
        float aa = 0.f;
        #pragma unroll 8
        for (int m = 0; m < 32; m++) {
            float zm = zsw[m];
            av = fmaf(zm, wv[m * 4 + h], av);
            aa = fmaf(zm, cks[m * 4 + h], aa);
        }
        ((float*)g_va)[(size_t)(e0w + e) * 8 + h] = av;
        ((float*)g_va)[(size_t)(e0w + e) * 8 + 4 + h] = aa;
    }

    // ---- store z fp16: lane = (edge e = lane>>2, chunk c = lane&3 of 8 halves)
    // FIX vs R12: each lane stores 8 halves (uint4), covering all 32 columns.
    {
        int e = lane >> 2, c = lane & 3;
        const float* zrow = zs + warp * 8 * ZSSTR + e * ZSSTR + 8 * c;
        float4 z0 = *(const float4*)(zrow);
        float4 z1 = *(const float4*)(zrow + 4);
        __half2 h0 = __floats2half2_rn(z0.x, z0.y);
        __half2 h1 = __floats2half2_rn(z0.z, z0.w);
        __half2 h2 = __floats2half2_rn(z1.x, z1.y);
        __half2 h3 = __floats2half2_rn(z1.z, z1.w);
        uint4 p;
        p.x = *(unsigned int*)&h0; p.y = *(unsigned int*)&h1;
        p.z = *(unsigned int*)&h2; p.w = *(unsigned int*)&h3;
        *(uint4*)(g_zh + (size_t)(e0w + e) * 32 + 8 * c) = p;
    }
}

// ---------------- K2: attention via fp16 MMA on gathered z ----------------
// Warp batch = 16 pairs. Gather Z_d/Z_s rows (64 B fp16), stage in SMEM
// (stride 40 halves: ldmatrix conflict-free), compute T = Z_d Mq_h and
// T2 = Z_s Mk_h via mma.m16n8k16, logits = rowdot(T,T2) + ak[s].
// Softmax-invariant q-side bias terms dropped exactly.
__global__ void __launch_bounds__(256) k_attn(const int* __restrict__ eei, int EE) {
    __shared__ __half zsm[8 * 2 * 16 * 40];   // per warp: d tile then s tile

    int tid = threadIdx.x;
    int lane = tid & 31;
    int warp = tid >> 5;
    int gwarp = blockIdx.x * 8 + warp;
    int b = gwarp * 16;
    if (b >= EE) return;

    __half* zd_s = zsm + warp * 2 * 16 * 40;
    __half* zs_s = zd_s + 16 * 40;

    // indices: lanes 0-15 -> es, 16-31 -> ed
    int li = __ldg(eei + ((lane < 16) ? (b + lane) : (EE + b + lane - 16)));

    // vsum / ak for es-side: lanes<16 vsum[es[lane]], lanes>=16 ak[es[lane-16]]
    int rr = lane & 15;
    int es_rr = __shfl_sync(FULLMASK, li, rr);
    float4 va = __ldg(g_va + 2 * (size_t)es_rr + (lane >> 4));

    // gather z rows: row r = lane>>1, 16-B chunks (lane&1) and (lane&1)+2
    {
        int r = lane >> 1;
        int ed_r = __shfl_sync(FULLMASK, li, 16 + r);
        int es_r = __shfl_sync(FULLMASK, li, r);
        #pragma unroll
        for (int k = 0; k < 2; k++) {
            int ch = (lane & 1) + 2 * k;
            uint4 vd = __ldg((const uint4*)(g_zh + (size_t)ed_r * 32) + ch);
            uint4 vs = __ldg((const uint4*)(g_zh + (size_t)es_r * 32) + ch);
            *(uint4*)(zd_s + r * 40 + ch * 8) = vd;
            *(uint4*)(zs_s + r * 40 + ch * 8) = vs;
        }
    }
    __syncwarp();

    // A fragments via ldmatrix (two k-chunks per side)
    unsigned ad[8], as_[8];
    {
        int zrow = lane & 15;
        int colh = (lane & 16) ? 8 : 0;
        unsigned a0 = smem_u32(zd_s + zrow * 40 + colh);
        unsigned a1 = smem_u32(zs_s + zrow * 40 + colh);
        asm volatile("ldmatrix.sync.aligned.m8n8.x4.shared.b16 {%0,%1,%2,%3}, [%4];"
            : "=r"(ad[0]), "=r"(ad[1]), "=r"(ad[2]), "=r"(ad[3]) : "r"(a0));
        asm volatile("ldmatrix.sync.aligned.m8n8.x4.shared.b16 {%0,%1,%2,%3}, [%4];"
            : "=r"(ad[4]), "=r"(ad[5]), "=r"(ad[6]), "=r"(ad[7]) : "r"(a0 + 32));
        asm volatile("ldmatrix.sync.aligned.m8n8.x4.shared.b16 {%0,%1,%2,%3}, [%4];"
            : "=r"(as_[0]), "=r"(as_[1]), "=r"(as_[2]), "=r"(as_[3]) : "r"(a1));
        asm volatile("ldmatrix.sync.aligned.m8n8.x4.shared.b16 {%0,%1,%2,%3}, [%4];"
            : "=r"(as_[4]), "=r"(as_[5]), "=r"(as_[6]), "=r"(as_[7]) : "r"(a1 + 32));
    }

    int r0 = lane >> 2;          // pair row for epilogue lanes (lane&3)==0
    int ed_r0 = __shfl_sync(FULLMASK, li, 16 + r0);
    int ed_r1 = __shfl_sync(FULLMASK, li, 24 + r0);

    #pragma unroll
    for (int h = 0; h < 4; h++) {
        float sg = 0.f, sg8 = 0.f;
        #pragma unroll
        for (int nt = 0; nt < 4; nt++) {
            int base = (((h * 2 + 0) * 4 + nt) * 4) * 32 + lane;  // side q
            unsigned bq0 = __ldg(g_mfrag + base);
            unsigned bq1 = __ldg(g_mfrag + base + 32);
            unsigned bq2 = __ldg(g_mfrag + base + 64);
            unsigned bq3 = __ldg(g_mfrag + base + 96);
            int basek = (((h * 2 + 1) * 4 + nt) * 4) * 32 + lane; // side k
            unsigned bk0 = __ldg(g_mfrag + basek);
            unsigned bk1 = __ldg(g_mfrag + basek + 32);
            unsigned bk2 = __ldg(g_mfrag + basek + 64);
            unsigned bk3 = __ldg(g_mfrag + basek + 96);

            float t0 = 0.f, t1 = 0.f, t2 = 0.f, t3 = 0.f;
            asm volatile("mma.sync.aligned.m16n8k16.row.col.f32.f16.f16.f32 "
                "{%0,%1,%2,%3}, {%4,%5,%6,%7}, {%8,%9}, {%0,%1,%2,%3};"
                : "+f"(t0), "+f"(t1), "+f"(t2), "+f"(t3)
                : "r"(ad[0]), "r"(ad[1]), "r"(ad[2]), "r"(ad[3]), "r"(bq0), "r"(bq1));
            asm volatile("mma.sync.aligned.m16n8k16.row.col.f32.f16.f16.f32 "
                "{%0,%1,%2,%3}, {%4,%5,%6,%7}, {%8,%9}, {%0,%1,%2,%3};"
                : "+f"(t0), "+f"(t1), "+f"(t2), "+f"(t3)
                : "r"(ad[4]), "r"(ad[5]), "r"(ad[6]), "r"(ad[7]), "r"(bq2), "r"(bq3));

            float u0 = 0.f, u1 = 0.f, u2 = 0.f, u3 = 0.f;
            asm volatile("mma.sync.aligned.m16n8k16.row.col.f32.f16.f16.f32 "
                "{%0,%1,%2,%3}, {%4,%5,%6,%7}, {%8,%9}, {%0,%1,%2,%3};"
                : "+f"(u0), "+f"(u1), "+f"(u2), "+f"(u3)
                : "r"(as_[0]), "r"(as_[1]), "r"(as_[2]), "r"(as_[3]), "r"(bk0), "r"(bk1));
            asm volatile("mma.sync.aligned.m16n8k16.row.col.f32.f16.f16.f32 "
                "{%0,%1,%2,%3}, {%4,%5,%6,%7}, {%8,%9}, {%0,%1,%2,%3};"
                : "+f"(u0), "+f"(u1), "+f"(u2), "+f"(u3)
                : "r"(as_[4]), "r"(as_[5]), "r"(as_[6]), "r"(as_[7]), "r"(bk2), "r"(bk3));

            sg  = fmaf(t0, u0, fmaf(t1, u1, sg));
            sg8 = fmaf(t2, u2, fmaf(t3, u3, sg8));
        }
        // reduce over the 4 lanes of the quad (t = lane&3)
        sg  += __shfl_xor_sync(FULLMASK, sg, 1);
        sg  += __shfl_xor_sync(FULLMASK, sg, 2);
        sg8 += __shfl_xor_sync(FULLMASK, sg8, 1);
        sg8 += __shfl_xor_sync(FULLMASK, sg8, 2);

        float vah = ((const float*)&va)[h];
        float ak0 = __shfl_sync(FULLMASK, vah, 16 + r0);
        float ak1 = __shfl_sync(FULLMASK, vah, 24 + r0);
        float vs0 = __shfl_sync(FULLMASK, vah, r0);
        float vs1 = __shfl_sync(FULLMASK, vah, 8 + r0);

        float ex0 = __expf(sg + ak0);
        float ex1 = __expf(sg8 + ak1);
        if ((lane & 3) == 0) {
            atomicAdd(&g_sn[(size_t)ed_r0 * 4 + h], make_float2(ex0, ex0 * vs0));
            atomicAdd(&g_sn[(size_t)ed_r1 * 4 + h], make_float2(ex1, ex1 * vs1));
        }
    }
}

// ---------------- K3: uef + stage3 messages (merged final pass) ----------------
__global__ void k_n3(float* __restrict__ out, const float* __restrict__ x,
                     const int* __restrict__ nni, int N, int E, int C) {
    int c = blockIdx.x * blockDim.x + threadIdx.x;
    if (c < E) {
        float4 a = ((const float4*)g_sn)[2 * c + 0];
        float4 b = ((const float4*)g_sn)[2 * c + 1];
        float u = a.y / (a.x + 1e-16f) + a.w / (a.z + 1e-16f)
                + b.y / (b.x + 1e-16f) + b.w / (b.z + 1e-16f);
        out[N + c] = u * (1.f / 128.f);
    }
    if (c < C) {
        int ns = nni[c], nd = nni[C + c];
        float xs = __ldg(x + ns);
        float s = xs * __ldg(x + nd);
        float4 S = g_S3[nd];
        const float* Sf = (const float*)&S;
        float acc = 0.f;
        #pragma unroll
        for (int h = 0; h < 4; h++) {
            float al = __expf(s * g_whk[h]) / (Sf[h] + 1e-16f);
            acc = fmaf(al, g_wv[h], acc);
        }
        atomicAdd(&out[nd], acc * xs * (1.f / 128.f));
    }
}

// ---------------- launch ----------------
extern "C" void kernel_launch(void* const* d_in, const int* in_sizes, int n_in,
                              void* d_out, int out_size) {
    const float* x   = (const float*)d_in[0];
    const int*   ei  = (const int*)d_in[1];
    const float* ea  = (const float*)d_in[2];
    const int*   eei = (const int*)d_in[3];
    const int*   nni = (const int*)d_in[4];
    const float* W1  = (const float*)d_in[5];
    const float* b1  = (const float*)d_in[6];
    const float* W2  = (const float*)d_in[7];
    const float* b2  = (const float*)d_in[8];
    const float* Wq  = (const float*)d_in[9];
    const float* Wk  = (const float*)d_in[10];
    const float* Wv  = (const float*)d_in[11];
    const float* Wq2 = (const float*)d_in[12];
    const float* Wk2 = (const float*)d_in[13];
    const float* Wv2 = (const float*)d_in[14];
    float* out = (float*)d_out;

    int N  = in_sizes[0];
    int E  = in_sizes[1] / 2;
    int EE = in_sizes[3] / 2;
    int C  = in_sizes[4] / 2;

    k_prep_all<<<(4480 + N + 255) / 256, 256>>>(W2, b2, Wq, Wk, Wv, Wq2, Wk2, Wv2, N);
    k_edge<<<(E + 63) / 64, 256>>>(x, ei, ea, W1, b1, nni, out, N, E, C);
    k_attn<<<(EE + 127) / 128, 256>>>(eei, EE);
    k_n3<<<(C + 255) / 256, 256>>>(out, x, nni, N, E, C);
}